// round 15
// baseline (speedup 1.0000x reference)
#include <cuda_runtime.h>
#include <cuda_bf16.h>
#include <cstdint>

#define DIM 80
#define DD 6400
#define D3 512000
#define NPTS 200000

typedef unsigned long long u64;
typedef unsigned int u32;

// ---------------------------------------------------------------------------
// Device scratch (no allocations in kernel_launch)
// ---------------------------------------------------------------------------
__device__ __nv_bfloat16 g_xhi[D3 * 32];
__device__ __nv_bfloat16 g_xlo[D3 * 32];
__device__ __nv_bfloat16 g_f1hi[D3 * 64];
__device__ __nv_bfloat16 g_f1lo[D3 * 64];
__device__ float         g_f2[D3 * 64];
__device__ __nv_bfloat16 g_w1hi[27 * 64 * 32], g_w1lo[27 * 64 * 32]; // [tap][oc][32c]
__device__ __nv_bfloat16 g_w2hi[27 * 64 * 64], g_w2lo[27 * 64 * 64];
__device__ __nv_bfloat16 g_mw1hi[256 * 64],  g_mw1lo[256 * 64];
__device__ __nv_bfloat16 g_mw2hi[256 * 256], g_mw2lo[256 * 256];
__device__ __nv_bfloat16 g_mw3hi[64 * 256],  g_mw3lo[64 * 256];

__device__ __forceinline__ u32 pkbf(__nv_bfloat16 a, __nv_bfloat16 b) {
    return (u32)__bfloat16_as_ushort(a) | ((u32)__bfloat16_as_ushort(b) << 16);
}

__device__ __forceinline__ void mma16816(float* d, const u32* a, const u32* b) {
    asm volatile(
        "mma.sync.aligned.m16n8k16.row.col.f32.bf16.bf16.f32 "
        "{%0,%1,%2,%3}, {%4,%5,%6,%7}, {%8,%9}, {%0,%1,%2,%3};"
        : "+f"(d[0]), "+f"(d[1]), "+f"(d[2]), "+f"(d[3])
        : "r"(a[0]), "r"(a[1]), "r"(a[2]), "r"(a[3]), "r"(b[0]), "r"(b[1]));
}

// ---------------------------------------------------------------------------
// Prep kernels
// ---------------------------------------------------------------------------
__global__ void prep_img(const float* __restrict__ img) {
    int p = blockIdx.x * 256 + threadIdx.x;
    u32 hw[16], lw[16];
    #pragma unroll
    for (int c = 0; c < 32; c += 2) {
        float a = img[c * D3 + p];
        float b = img[(c + 1) * D3 + p];
        __nv_bfloat16 ah = __float2bfloat16_rn(a);
        __nv_bfloat16 al = __float2bfloat16_rn(a - __bfloat162float(ah));
        __nv_bfloat16 bh = __float2bfloat16_rn(b);
        __nv_bfloat16 bl = __float2bfloat16_rn(b - __bfloat162float(bh));
        hw[c >> 1] = pkbf(ah, bh);
        lw[c >> 1] = pkbf(al, bl);
    }
    uint4* oh = (uint4*)(g_xhi + (size_t)p * 32);
    uint4* ol = (uint4*)(g_xlo + (size_t)p * 32);
    #pragma unroll
    for (int q = 0; q < 4; q++) {
        oh[q] = make_uint4(hw[q*4], hw[q*4+1], hw[q*4+2], hw[q*4+3]);
        ol[q] = make_uint4(lw[q*4], lw[q*4+1], lw[q*4+2], lw[q*4+3]);
    }
}

__global__ void prep_w1(const float* __restrict__ w) {
    int idx = blockIdx.x * 256 + threadIdx.x;
    if (idx >= 27 * 2048) return;
    int j = idx >> 11, r = idx & 2047, o = r >> 5, c = r & 31;
    float v = w[(o * 32 + c) * 27 + j];
    __nv_bfloat16 h = __float2bfloat16_rn(v);
    g_w1hi[idx] = h;
    g_w1lo[idx] = __float2bfloat16_rn(v - __bfloat162float(h));
}
__global__ void prep_w2(const float* __restrict__ w) {
    int idx = blockIdx.x * 256 + threadIdx.x;
    if (idx >= 27 * 4096) return;
    int j = idx >> 12, r = idx & 4095, o = r >> 6, c = r & 63;
    float v = w[(o * 64 + c) * 27 + j];
    __nv_bfloat16 h = __float2bfloat16_rn(v);
    g_w2hi[idx] = h;
    g_w2lo[idx] = __float2bfloat16_rn(v - __bfloat162float(h));
}

__global__ void prep_wmlp(const float* __restrict__ src,
                          __nv_bfloat16* __restrict__ dhi,
                          __nv_bfloat16* __restrict__ dlo, int n) {
    int i = blockIdx.x * 256 + threadIdx.x;
    if (i >= n) return;
    float v = src[i];
    __nv_bfloat16 h = __float2bfloat16_rn(v);
    dhi[i] = h;
    dlo[i] = __float2bfloat16_rn(v - __bfloat162float(h));
}

#define RSTR 144
#define AROWS 130

// ---------------------------------------------------------------------------
// Conv1 with halo tiling — unchanged from R14
// ---------------------------------------------------------------------------
#define C1_W_BASE (AROWS * RSTR)              // 18720
#define C1_W_TAP  (64 * RSTR)                 // 9216
#define SMEM_CONV1 (C1_W_BASE + 3 * C1_W_TAP) // 46368

__global__ __launch_bounds__(256, 3) void conv1_halo(const float* __restrict__ bias)
{
    extern __shared__ char smem[];
    const int tid = threadIdx.x;
    const int warp = tid >> 5, lane = tid & 31;
    const int p0 = blockIdx.x * 128;
    const int wm = warp >> 1, wn = warp & 1;
    const int g = lane >> 2, tg = lane & 3;

    int xr0[2], xr1[2];
    #pragma unroll
    for (int mt = 0; mt < 2; mt++) {
        int pr = p0 + wm * 32 + mt * 16 + g;
        xr0[mt] = pr % 80;
        xr1[mt] = (pr + 8) % 80;
    }

    float acc[2][4][4];
    #pragma unroll
    for (int mt = 0; mt < 2; mt++)
        #pragma unroll
        for (int nt = 0; nt < 4; nt++)
            #pragma unroll
            for (int q = 0; q < 4; q++) acc[mt][nt][q] = 0.f;

    for (int jzy = 0; jzy < 9; jzy++) {
        const int kz = jzy / 3, ky = jzy - kz * 3;
        __syncthreads();
        for (int i = tid; i < AROWS * 8; i += 256) {
            int r = i >> 3, t = i & 7;
            int q = p0 + r - 1;
            bool v = (q >= 0) && (q < D3);
            int zq = 0, yq = 0;
            if (v) { zq = q / DD; int r2 = q - zq * DD; yq = r2 / DIM; }
            v = v && (unsigned)(zq + kz - 1) < 80u &&
                     (unsigned)(yq + ky - 1) < 80u;
            u32 off = r * RSTR + ((t & 4) ? 64 : 0) + (t & 3) * 16;
            if (v) {
                int ps = q + (kz - 1) * DD + (ky - 1) * DIM;
                const uint4* src = (t < 4)
                    ? (const uint4*)(g_xhi + (size_t)ps * 32) + t
                    : (const uint4*)(g_xlo + (size_t)ps * 32) + (t - 4);
                *(uint4*)(smem + off) = *src;
            } else {
                *(uint4*)(smem + off) = make_uint4(0, 0, 0, 0);
            }
        }
        #pragma unroll
        for (int kx = 0; kx < 3; kx++) {
            int j = jzy * 3 + kx;
            const uint4* wh = (const uint4*)(g_w1hi + j * 2048);
            const uint4* wl = (const uint4*)(g_w1lo + j * 2048);
            #pragma unroll
            for (int u = tid; u < 512; u += 256) {
                int r = u >> 3, t = u & 7;
                u32 off = C1_W_BASE + kx * C1_W_TAP + r * RSTR +
                          ((t & 4) ? 64 : 0) + (t & 3) * 16;
                *(uint4*)(smem + off) = (t < 4) ? wh[r * 4 + t]
                                                : wl[r * 4 + (t - 4)];
            }
        }
        __syncthreads();

        #pragma unroll
        for (int kx = 0; kx < 3; kx++) {
            const char* wp = smem + C1_W_BASE + kx * C1_W_TAP;
            #pragma unroll
            for (int ks = 0; ks < 2; ks++) {
                u32 bh[4][2], bl[4][2];
                #pragma unroll
                for (int nt = 0; nt < 4; nt++) {
                    u32 base = (wn * 32 + nt * 8 + g) * RSTR + ks * 32 + tg * 4;
                    bh[nt][0] = *(const u32*)(wp + base);
                    bh[nt][1] = *(const u32*)(wp + base + 16);
                    bl[nt][0] = *(const u32*)(wp + base + 64);
                    bl[nt][1] = *(const u32*)(wp + base + 64 + 16);
                }
                #pragma unroll
                for (int mt = 0; mt < 2; mt++) {
                    bool va = (kx == 1) ||
                              (kx == 0 ? (xr0[mt] != 0) : (xr0[mt] != 79));
                    bool vb = (kx == 1) ||
                              (kx == 0 ? (xr1[mt] != 0) : (xr1[mt] != 79));
                    u32 base = (wm * 32 + mt * 16 + g + kx) * RSTR +
                               ks * 32 + tg * 4;
                    u32 ah[4], al[4];
                    ah[0] = va ? *(const u32*)(smem + base) : 0u;
                    ah[1] = vb ? *(const u32*)(smem + base + 8 * RSTR) : 0u;
                    ah[2] = va ? *(const u32*)(smem + base + 16) : 0u;
                    ah[3] = vb ? *(const u32*)(smem + base + 8 * RSTR + 16) : 0u;
                    al[0] = va ? *(const u32*)(smem + base + 64) : 0u;
                    al[1] = vb ? *(const u32*)(smem + base + 64 + 8 * RSTR) : 0u;
                    al[2] = va ? *(const u32*)(smem + base + 64 + 16) : 0u;
                    al[3] = vb ? *(const u32*)(smem + base + 64 + 8 * RSTR + 16) : 0u;
                    #pragma unroll
                    for (int nt = 0; nt < 4; nt++) {
                        mma16816(acc[mt][nt], ah, bh[nt]);
                        mma16816(acc[mt][nt], ah, bl[nt]);
                        mma16816(acc[mt][nt], al, bh[nt]);
                    }
                }
            }
        }
    }

    #pragma unroll
    for (int mt = 0; mt < 2; mt++) {
        #pragma unroll
        for (int nt = 0; nt < 4; nt++) {
            const int n = wn * 32 + nt * 8 + tg * 2;
            const float b0 = __ldg(bias + n), b1 = __ldg(bias + n + 1);
            const int pixA = p0 + wm * 32 + mt * 16 + g;
            const int pixB = pixA + 8;
            float v0 = fmaxf(acc[mt][nt][0] + b0, 0.f);
            float v1 = fmaxf(acc[mt][nt][1] + b1, 0.f);
            float v2 = fmaxf(acc[mt][nt][2] + b0, 0.f);
            float v3 = fmaxf(acc[mt][nt][3] + b1, 0.f);
            __nv_bfloat16 h0 = __float2bfloat16_rn(v0);
            __nv_bfloat16 h1 = __float2bfloat16_rn(v1);
            __nv_bfloat16 h2 = __float2bfloat16_rn(v2);
            __nv_bfloat16 h3 = __float2bfloat16_rn(v3);
            *(u32*)(g_f1hi + (size_t)pixA * 64 + n) = pkbf(h0, h1);
            *(u32*)(g_f1hi + (size_t)pixB * 64 + n) = pkbf(h2, h3);
            *(u32*)(g_f1lo + (size_t)pixA * 64 + n) =
                pkbf(__float2bfloat16_rn(v0 - __bfloat162float(h0)),
                     __float2bfloat16_rn(v1 - __bfloat162float(h1)));
            *(u32*)(g_f1lo + (size_t)pixB * 64 + n) =
                pkbf(__float2bfloat16_rn(v2 - __bfloat162float(h2)),
                     __float2bfloat16_rn(v3 - __bfloat162float(h3)));
        }
    }
}

// ---------------------------------------------------------------------------
// Conv2 halo + 2-slot W double buffer — unchanged from R14
// ---------------------------------------------------------------------------
#define A2_HI 0
#define A2_LO (AROWS * RSTR)                  // 18720
#define W2_BASE (2 * AROWS * RSTR)            // 37440
#define W2_TAP (2 * 64 * RSTR)                // 18432
#define SMEM_CONV2 (W2_BASE + 2 * W2_TAP)     // 74304

__device__ __forceinline__ void c2_stage_w(char* smem, int j, int slot, int tid)
{
    const uint4* wh = (const uint4*)(g_w2hi + j * 4096);
    const uint4* wl = (const uint4*)(g_w2lo + j * 4096);
    #pragma unroll
    for (int u = tid; u < 512; u += 256) {
        u32 off = (u >> 3) * RSTR + (u & 7) * 16;
        *(uint4*)(smem + W2_BASE + slot * W2_TAP + off) = wh[u];
        *(uint4*)(smem + W2_BASE + slot * W2_TAP + 9216 + off) = wl[u];
    }
}

__global__ __launch_bounds__(256, 3) void conv2_halo(const float* __restrict__ bias)
{
    extern __shared__ char smem[];
    const int tid = threadIdx.x;
    const int warp = tid >> 5, lane = tid & 31;
    const int p0 = blockIdx.x * 128;
    const int wm = warp >> 1, wn = warp & 1;
    const int g = lane >> 2, tg = lane & 3;

    int xr0[2], xr1[2];
    #pragma unroll
    for (int mt = 0; mt < 2; mt++) {
        int pr = p0 + wm * 32 + mt * 16 + g;
        xr0[mt] = pr % 80;
        xr1[mt] = (pr + 8) % 80;
    }

    float acc[2][4][4];
    #pragma unroll
    for (int mt = 0; mt < 2; mt++)
        #pragma unroll
        for (int nt = 0; nt < 4; nt++)
            #pragma unroll
            for (int q = 0; q < 4; q++) acc[mt][nt][q] = 0.f;

    for (int jzy = 0; jzy < 9; jzy++) {
        const int kz = jzy / 3, ky = jzy - kz * 3;
        __syncthreads();
        for (int i = tid; i < 2 * AROWS; i += 256) {
            int r = i >> 1, h = i & 1;
            int q = p0 + r - 1;
            bool v = (q >= 0) && (q < D3);
            int zq = 0, yq = 0;
            if (v) { zq = q / DD; int r2 = q - zq * DD; yq = r2 / DIM; }
            v = v && (unsigned)(zq + kz - 1) < 80u &&
                     (unsigned)(yq + ky - 1) < 80u;
            u32 off = r * RSTR + h * 64;
            if (v) {
                int ps = q + (kz - 1) * DD + (ky - 1) * DIM;
                const uint4* shi = (const uint4*)(g_f1hi + (size_t)ps * 64) + h * 4;
                const uint4* slo = (const uint4*)(g_f1lo + (size_t)ps * 64) + h * 4;
                #pragma unroll
                for (int t = 0; t < 4; t++) {
                    *(uint4*)(smem + A2_HI + off + t * 16) = shi[t];
                    *(uint4*)(smem + A2_LO + off + t * 16) = slo[t];
                }
            } else {
                const uint4 zero = make_uint4(0, 0, 0, 0);
                #pragma unroll
                for (int t = 0; t < 4; t++) {
                    *(uint4*)(smem + A2_HI + off + t * 16) = zero;
                    *(uint4*)(smem + A2_LO + off + t * 16) = zero;
                }
            }
        }
        c2_stage_w(smem, jzy * 3 + 0, 0, tid);
        c2_stage_w(smem, jzy * 3 + 1, 1, tid);
        __syncthreads();

        #pragma unroll
        for (int phase = 0; phase < 2; phase++) {
            const int nkx = (phase == 0) ? 2 : 1;
            for (int s = 0; s < nkx; s++) {
                const int kx = (phase == 0) ? s : 2;
                const char* wp = smem + W2_BASE + ((phase == 0) ? s : 0) * W2_TAP;
                #pragma unroll
                for (int ks = 0; ks < 4; ks++) {
                    u32 bh[4][2], bl[4][2];
                    #pragma unroll
                    for (int nt = 0; nt < 4; nt++) {
                        u32 base = (wn * 32 + nt * 8 + g) * RSTR + ks * 32 + tg * 4;
                        bh[nt][0] = *(const u32*)(wp + base);
                        bh[nt][1] = *(const u32*)(wp + base + 16);
                        bl[nt][0] = *(const u32*)(wp + 9216 + base);
                        bl[nt][1] = *(const u32*)(wp + 9216 + base + 16);
                    }
                    #pragma unroll
                    for (int mt = 0; mt < 2; mt++) {
                        bool va = (kx == 1) ||
                                  (kx == 0 ? (xr0[mt] != 0) : (xr0[mt] != 79));
                        bool vb = (kx == 1) ||
                                  (kx == 0 ? (xr1[mt] != 0) : (xr1[mt] != 79));
                        u32 base = (wm * 32 + mt * 16 + g + kx) * RSTR +
                                   ks * 32 + tg * 4;
                        u32 ah[4], al[4];
                        ah[0] = va ? *(const u32*)(smem + A2_HI + base) : 0u;
                        ah[1] = vb ? *(const u32*)(smem + A2_HI + base + 8 * RSTR) : 0u;
                        ah[2] = va ? *(const u32*)(smem + A2_HI + base + 16) : 0u;
                        ah[3] = vb ? *(const u32*)(smem + A2_HI + base + 8 * RSTR + 16) : 0u;
                        al[0] = va ? *(const u32*)(smem + A2_LO + base) : 0u;
                        al[1] = vb ? *(const u32*)(smem + A2_LO + base + 8 * RSTR) : 0u;
                        al[2] = va ? *(const u32*)(smem + A2_LO + base + 16) : 0u;
                        al[3] = vb ? *(const u32*)(smem + A2_LO + base + 8 * RSTR + 16) : 0u;
                        #pragma unroll
                        for (int nt = 0; nt < 4; nt++) {
                            mma16816(acc[mt][nt], ah, bh[nt]);
                            mma16816(acc[mt][nt], ah, bl[nt]);
                            mma16816(acc[mt][nt], al, bh[nt]);
                        }
                    }
                }
            }
            if (phase == 0) {
                __syncthreads();
                c2_stage_w(smem, jzy * 3 + 2, 0, tid);
                __syncthreads();
            }
        }
    }

    #pragma unroll
    for (int mt = 0; mt < 2; mt++) {
        #pragma unroll
        for (int nt = 0; nt < 4; nt++) {
            const int n = wn * 32 + nt * 8 + tg * 2;
            const float b0 = __ldg(bias + n), b1 = __ldg(bias + n + 1);
            const int pixA = p0 + wm * 32 + mt * 16 + g;
            const int pixB = pixA + 8;
            float v0 = fmaxf(acc[mt][nt][0] + b0, 0.f);
            float v1 = fmaxf(acc[mt][nt][1] + b1, 0.f);
            float v2 = fmaxf(acc[mt][nt][2] + b0, 0.f);
            float v3 = fmaxf(acc[mt][nt][3] + b1, 0.f);
            *(float2*)(g_f2 + (size_t)pixA * 64 + n) = make_float2(v0, v1);
            *(float2*)(g_f2 + (size_t)pixB * 64 + n) = make_float2(v2, v3);
        }
    }
}

// ---------------------------------------------------------------------------
// Fused MLP: gather + L1(64->256) + L2(256->256) + L3(256->64) + L4(64->6)
// 64 points/block, 3125 blocks (exact), all activations in smem.
// Smem: X hi/lo @0 (18432; later reused as H3 fp32, stride 66 floats)
//       H1 @18432 (4 chunks x 18432), H2 @92160 (4 x 18432)
//       WB ping-pong @165888 (2 x 18432).  Total 202752.
// 24 steps: L1 nc0-3 | L2 (nc,kc) 4x4 | L3 kc0-3. W staged via issue/commit
// ping-pong (LDG before MMAs, STS after), 1 barrier per step.
// ---------------------------------------------------------------------------
#define FM_XHI 0
#define FM_H1  18432
#define FM_H2  92160
#define FM_WB  165888
#define SMEM_FM 202752
#define H3STR 264    // 66 floats per row

__device__ __forceinline__ void fm_decode(int s, int& L, int& nc, int& kc) {
    if (s < 4)       { L = 1; nc = s;            kc = 0; }
    else if (s < 20) { L = 2; nc = (s - 4) >> 2; kc = (s - 4) & 3; }
    else             { L = 3; nc = 0;            kc = s - 20; }
}

__device__ __forceinline__ void fm_wsrc(int L, const __nv_bfloat16*& Whi,
                                        const __nv_bfloat16*& Wlo, int& cin) {
    if (L == 1)      { Whi = g_mw1hi; Wlo = g_mw1lo; cin = 64; }
    else if (L == 2) { Whi = g_mw2hi; Wlo = g_mw2lo; cin = 256; }
    else             { Whi = g_mw3hi; Wlo = g_mw3lo; cin = 256; }
}

__global__ __launch_bounds__(256) void fused_mlp(
    const int* __restrict__ c0, const int* __restrict__ c1,
    const int* __restrict__ c2,
    const float* __restrict__ b1, const float* __restrict__ b2,
    const float* __restrict__ b3,
    const float* __restrict__ w4, const float* __restrict__ b4,
    float* __restrict__ out)
{
    extern __shared__ char smem[];
    const int tid = threadIdx.x;
    const int warp = tid >> 5, lane = tid & 31;
    const int wm = warp >> 2, wn = warp & 3;     // 2m x 4n warps
    const int g = lane >> 2, tg = lane & 3;
    const int n0 = blockIdx.x * 64;

    // ---- initial: gather X (threads 0-127) + stage step-0 W (threads 128-255)
    if (tid < 128) {
        int m = tid >> 1, half = tid & 1;
        int n = n0 + m;
        int vox = c0[n] * DD + c1[n] * DIM + c2[n];
        const float4* src = (const float4*)(g_f2 + (size_t)vox * 64 + half * 32);
        u32 hw[16], lw[16];
        #pragma unroll
        for (int i = 0; i < 8; i++) {
            float4 q = src[i];
            __nv_bfloat16 ah = __float2bfloat16_rn(q.x);
            __nv_bfloat16 al = __float2bfloat16_rn(q.x - __bfloat162float(ah));
            __nv_bfloat16 bh = __float2bfloat16_rn(q.y);
            __nv_bfloat16 bl = __float2bfloat16_rn(q.y - __bfloat162float(bh));
            hw[2*i]   = pkbf(ah, bh);
            lw[2*i]   = pkbf(al, bl);
            ah = __float2bfloat16_rn(q.z);
            al = __float2bfloat16_rn(q.z - __bfloat162float(ah));
            bh = __float2bfloat16_rn(q.w);
            bl = __float2bfloat16_rn(q.w - __bfloat162float(bh));
            hw[2*i+1] = pkbf(ah, bh);
            lw[2*i+1] = pkbf(al, bl);
        }
        #pragma unroll
        for (int i = 0; i < 4; i++) {
            u32 off = FM_XHI + m * RSTR + half * 64 + i * 16;
            *(uint4*)(smem + off) =
                make_uint4(hw[4*i], hw[4*i+1], hw[4*i+2], hw[4*i+3]);
            *(uint4*)(smem + off + 9216) =
                make_uint4(lw[4*i], lw[4*i+1], lw[4*i+2], lw[4*i+3]);
        }
    } else {
        // stage step 0 weights (L1, nc=0, kc=0) into slot 0
        for (int u = tid - 128; u < 512; u += 128) {
            int r = u >> 3, q = u & 7;
            const uint4* sh = (const uint4*)(g_mw1hi + (size_t)r * 64) + q;
            const uint4* sl = (const uint4*)(g_mw1lo + (size_t)r * 64) + q;
            u32 off = FM_WB + r * RSTR + q * 16;
            *(uint4*)(smem + off) = *sh;
            *(uint4*)(smem + off + 9216) = *sl;
        }
    }
    __syncthreads();

    float acc[2][2][4];
    uint4 wv[4];
    u32 woff[4];

    #pragma unroll 1
    for (int s = 0; s < 24; s++) {
        int L, nc, kc;
        fm_decode(s, L, nc, kc);

        // ---- issue prefetch of step s+1 weights (LDG only)
        const bool pf = (s < 23);
        if (pf) {
            int Ln, ncn, kcn;
            fm_decode(s + 1, Ln, ncn, kcn);
            const __nv_bfloat16 *Whi, *Wlo; int cin;
            fm_wsrc(Ln, Whi, Wlo, cin);
            int slot = (s + 1) & 1;
            #pragma unroll
            for (int it = 0; it < 2; it++) {
                int u = tid + it * 256;
                int r = u >> 3, q = u & 7;
                const uint4* sh =
                    (const uint4*)(Whi + (size_t)(ncn * 64 + r) * cin + kcn * 64) + q;
                const uint4* sl =
                    (const uint4*)(Wlo + (size_t)(ncn * 64 + r) * cin + kcn * 64) + q;
                wv[it*2]     = *sh;
                wv[it*2 + 1] = *sl;
                woff[it*2]     = FM_WB + slot * 18432 + r * RSTR + q * 16;
                woff[it*2 + 1] = woff[it*2] + 9216;
            }
        }

        // ---- compute step s
        if (kc == 0) {
            #pragma unroll
            for (int mt = 0; mt < 2; mt++)
                #pragma unroll
                for (int nt = 0; nt < 2; nt++)
                    #pragma unroll
                    for (int q = 0; q < 4; q++) acc[mt][nt][q] = 0.f;
        }
        {
            const int in_off = (L == 1) ? FM_XHI
                             : (L == 2) ? FM_H1 + kc * 18432
                                        : FM_H2 + kc * 18432;
            const char* wb = smem + FM_WB + (s & 1) * 18432;
            #pragma unroll
            for (int ks = 0; ks < 4; ks++) {
                u32 bh[2][2], bl[2][2];
                #pragma unroll
                for (int nt = 0; nt < 2; nt++) {
                    u32 base = (wn * 16 + nt * 8 + g) * RSTR + ks * 32 + tg * 4;
                    bh[nt][0] = *(const u32*)(wb + base);
                    bh[nt][1] = *(const u32*)(wb + base + 16);
                    bl[nt][0] = *(const u32*)(wb + 9216 + base);
                    bl[nt][1] = *(const u32*)(wb + 9216 + base + 16);
                }
                #pragma unroll
                for (int mt = 0; mt < 2; mt++) {
                    u32 base = in_off + (wm * 32 + mt * 16 + g) * RSTR +
                               ks * 32 + tg * 4;
                    u32 ah[4], al[4];
                    ah[0] = *(const u32*)(smem + base);
                    ah[1] = *(const u32*)(smem + base + 8 * RSTR);
                    ah[2] = *(const u32*)(smem + base + 16);
                    ah[3] = *(const u32*)(smem + base + 8 * RSTR + 16);
                    al[0] = *(const u32*)(smem + base + 9216);
                    al[1] = *(const u32*)(smem + base + 9216 + 8 * RSTR);
                    al[2] = *(const u32*)(smem + base + 9216 + 16);
                    al[3] = *(const u32*)(smem + base + 9216 + 8 * RSTR + 16);
                    #pragma unroll
                    for (int nt = 0; nt < 2; nt++) {
                        mma16816(acc[mt][nt], ah, bh[nt]);
                        mma16816(acc[mt][nt], ah, bl[nt]);
                        mma16816(acc[mt][nt], al, bh[nt]);
                    }
                }
            }
        }

        // ---- epilogue on last k-chunk of this (layer, nc)
        const bool last = (L == 1) || (kc == 3);
        if (last) {
            #pragma unroll
            for (int mt = 0; mt < 2; mt++) {
                #pragma unroll
                for (int nt = 0; nt < 2; nt++) {
                    const int col = wn * 16 + nt * 8 + tg * 2;
                    const int rowA = wm * 32 + mt * 16 + g;
                    const int rowB = rowA + 8;
                    if (L < 3) {
                        const float* bias = (L == 1) ? b1 : b2;
                        const int gc = nc * 64 + col;
                        float bb0 = __ldg(bias + gc), bb1 = __ldg(bias + gc + 1);
                        float v0 = fmaxf(acc[mt][nt][0] + bb0, 0.f);
                        float v1 = fmaxf(acc[mt][nt][1] + bb1, 0.f);
                        float v2 = fmaxf(acc[mt][nt][2] + bb0, 0.f);
                        float v3 = fmaxf(acc[mt][nt][3] + bb1, 0.f);
                        u32 ob = ((L == 1) ? FM_H1 : FM_H2) + nc * 18432;
                        __nv_bfloat16 h0 = __float2bfloat16_rn(v0);
                        __nv_bfloat16 h1 = __float2bfloat16_rn(v1);
                        __nv_bfloat16 h2 = __float2bfloat16_rn(v2);
                        __nv_bfloat16 h3 = __float2bfloat16_rn(v3);
                        *(u32*)(smem + ob + rowA * RSTR + col * 2) = pkbf(h0, h1);
                        *(u32*)(smem + ob + rowB * RSTR + col * 2) = pkbf(h2, h3);
                        *(u32*)(smem + ob + 9216 + rowA * RSTR + col * 2) =
                            pkbf(__float2bfloat16_rn(v0 - __bfloat162float(h0)),
                                 __float2bfloat16_rn(v1 - __bfloat162float(h1)));
                        *(u32*)(smem + ob + 9216 + rowB * RSTR + col * 2) =
                            pkbf(__float2bfloat16_rn(v2 - __bfloat162float(h2)),
                                 __float2bfloat16_rn(v3 - __bfloat162float(h3)));
                    } else {
                        float bb0 = __ldg(b3 + col), bb1 = __ldg(b3 + col + 1);
                        *(float2*)(smem + rowA * H3STR + col * 4) =
                            make_float2(acc[mt][nt][0] + bb0, acc[mt][nt][1] + bb1);
                        *(float2*)(smem + rowB * H3STR + col * 4) =
                            make_float2(acc[mt][nt][2] + bb0, acc[mt][nt][3] + bb1);
                    }
                }
            }
        }

        // ---- commit prefetch stores
        if (pf) {
            #pragma unroll
            for (int j = 0; j < 4; j++)
                *(uint4*)(smem + woff[j]) = wv[j];
        }
        __syncthreads();
    }

    // ---- L4: 6 outs x 64 points from H3 (fp32 in smem)
    for (int i = tid; i < 384; i += 256) {
        int o = i >> 6, pt = i & 63;
        float a = __ldg(b4 + o);
        const float* xr = (const float*)(smem + pt * H3STR);
        #pragma unroll
        for (int c = 0; c < 64; c++)
            a = fmaf(__ldg(w4 + o * 64 + c), xr[c], a);
        out[(size_t)o * NPTS + n0 + pt] = a;
    }
}

// ---------------------------------------------------------------------------
extern "C" void kernel_launch(void* const* d_in, const int* in_sizes, int n_in,
                              void* d_out, int out_size)
{
    const float* img = (const float*)d_in[0];
    const int*   c0  = (const int*)d_in[1];
    const int*   c1  = (const int*)d_in[2];
    const int*   c2  = (const int*)d_in[3];
    const float* we1 = (const float*)d_in[4];
    const float* be1 = (const float*)d_in[5];
    const float* we2 = (const float*)d_in[6];
    const float* be2 = (const float*)d_in[7];
    const float* wp1 = (const float*)d_in[8];
    const float* bp1 = (const float*)d_in[9];
    const float* wp2 = (const float*)d_in[10];
    const float* bp2 = (const float*)d_in[11];
    const float* wp3 = (const float*)d_in[12];
    const float* bp3 = (const float*)d_in[13];
    const float* wp4 = (const float*)d_in[14];
    const float* bp4 = (const float*)d_in[15];
    float* out = (float*)d_out;

    cudaFuncSetAttribute(conv1_halo,
                         cudaFuncAttributeMaxDynamicSharedMemorySize, SMEM_CONV1);
    cudaFuncSetAttribute(conv2_halo,
                         cudaFuncAttributeMaxDynamicSharedMemorySize, SMEM_CONV2);
    cudaFuncSetAttribute(fused_mlp,
                         cudaFuncAttributeMaxDynamicSharedMemorySize, SMEM_FM);

    __nv_bfloat16 *mw1hi, *mw1lo, *mw2hi, *mw2lo, *mw3hi, *mw3lo;
    cudaGetSymbolAddress((void**)&mw1hi, g_mw1hi);
    cudaGetSymbolAddress((void**)&mw1lo, g_mw1lo);
    cudaGetSymbolAddress((void**)&mw2hi, g_mw2hi);
    cudaGetSymbolAddress((void**)&mw2lo, g_mw2lo);
    cudaGetSymbolAddress((void**)&mw3hi, g_mw3hi);
    cudaGetSymbolAddress((void**)&mw3lo, g_mw3lo);

    prep_img<<<2000, 256>>>(img);
    prep_w1<<<(27 * 2048 + 255) / 256, 256>>>(we1);
    prep_w2<<<(27 * 4096 + 255) / 256, 256>>>(we2);
    prep_wmlp<<<(256 * 64 + 255) / 256, 256>>>(wp1, mw1hi, mw1lo, 256 * 64);
    prep_wmlp<<<(256 * 256 + 255) / 256, 256>>>(wp2, mw2hi, mw2lo, 256 * 256);
    prep_wmlp<<<(64 * 256 + 255) / 256, 256>>>(wp3, mw3hi, mw3lo, 64 * 256);

    conv1_halo<<<4000, 256, SMEM_CONV1>>>(be1);
    conv2_halo<<<4000, 256, SMEM_CONV2>>>(be2);

    fused_mlp<<<NPTS / 64, 256, SMEM_FM>>>(c0, c1, c2, bp1, bp2, bp3,
                                           wp4, bp4, out);
}